// round 10
// baseline (speedup 1.0000x reference)
#include <cuda_runtime.h>
#include <cstdint>

// out[t,b,i,e] = x[t,b,i] * W[i,e] + b[e];  T=8,B=64,D=512,E=256; k=t*B+b.
// R9 experiment: TMA bulk store path. Each block computes a 32-row x 1KB tile
// (fixed i, 32 consecutive k) into SMEM, then drains it with 32x 1KB
// cp.async.bulk.global.shared::cta ops — bypassing the per-warp L1 STG
// wavefront path that has been pinned at DRAM=65% for five rounds.

#define D_DIM 512
#define E4    64          // float4 per row
#define K_PER_BLK 32
#define K_CHUNKS  16      // 512 / 32

__global__ __launch_bounds__(256) void dense_embed_kernel(
    const float* __restrict__ x,    // [512 * 512]
    const float4* __restrict__ W4,  // [512 * 64]
    const float4* __restrict__ b4,  // [64]
    float4* __restrict__ out4)      // [512 * 512 * 64]
{
    __shared__ __align__(128) float4 tile[K_PER_BLK * E4];   // 32KB

    const unsigned i  = blockIdx.x;                // 0..511
    const unsigned k0 = blockIdx.y * K_PER_BLK;    // 0,32,..,480
    const unsigned e4 = threadIdx.x & (E4 - 1);    // 0..63
    const unsigned kg = threadIdx.x >> 6;          // 0..3 (8 rows each)

    const float4 w  = __ldg(&W4[i * E4 + e4]);
    const float4 bb = __ldg(&b4[e4]);
    const float* xp = x + (size_t)k0 * D_DIM + i;

    // Batch the 8 x-loads for this thread's rows (independent, overlapped).
    float xv[8];
    #pragma unroll
    for (int r = 0; r < 8; r++)
        xv[r] = __ldg(&xp[(size_t)(kg * 8 + r) * D_DIM]);

    #pragma unroll
    for (int r = 0; r < 8; r++) {
        float4 o;
        o.x = fmaf(xv[r], w.x, bb.x);
        o.y = fmaf(xv[r], w.y, bb.y);
        o.z = fmaf(xv[r], w.z, bb.z);
        o.w = fmaf(xv[r], w.w, bb.w);
        tile[(kg * 8 + r) * E4 + e4] = o;
    }
    __syncthreads();

    // Async-proxy must see the generic-proxy SMEM writes.
    asm volatile("fence.proxy.async.shared::cta;" ::: "memory");

    // Warp 0: 32 bulk stores of 1KB each (one per k-row; rows are the
    // contiguous units of the output — k-stride is 512*1KB).
    if (threadIdx.x < K_PER_BLK) {
        const unsigned row = threadIdx.x;
        float4* dst = out4 + ((size_t)(k0 + row) * D_DIM + i) * E4;
        uint32_t src;
        asm("{ .reg .u64 t; cvta.to.shared.u64 t, %1; cvt.u32.u64 %0, t; }"
            : "=r"(src) : "l"(&tile[row * E4]));
        asm volatile(
            "cp.async.bulk.global.shared::cta.bulk_group [%0], [%1], %2;"
            :: "l"(dst), "r"(src), "n"(E4 * 16) : "memory");
        asm volatile("cp.async.bulk.commit_group;" ::: "memory");
        asm volatile("cp.async.bulk.wait_group 0;" ::: "memory");
    }
    // Non-issuing warps may exit; SMEM is freed only at full-block completion,
    // which is gated by warp 0's wait_group.
}

extern "C" void kernel_launch(void* const* d_in, const int* in_sizes, int n_in,
                              void* d_out, int out_size) {
    const float*  x  = (const float*)d_in[0];
    const float4* W4 = (const float4*)d_in[1];
    const float4* b4 = (const float4*)d_in[2];
    float4* out4 = (float4*)d_out;

    dim3 grid(D_DIM, K_CHUNKS);   // 512 x 16 = 8192 blocks
    dense_embed_kernel<<<grid, 256>>>(x, W4, b4, out4);
}